// round 14
// baseline (speedup 1.0000x reference)
#include <cuda_runtime.h>
#include <cuda_bf16.h>

#define NN 50000
#define NE 800000
#define IN_DIM 166
#define HID 128
#define BN_EPS 1e-5f
#define SCAN_NB 196   // ceil(NN/256)
#define H0 25088      // node split point (multiple of 128)

#define KP0 176                    // padded K for layer 0
#define W0SZ (KP0 * HID)           // 22528 words per layer-0 weight
#define W1SZ (HID * HID)           // 16384 words per layer-1 weight

// ---------------- scratch ----------------
__device__ int    g_deg[NN];           // statically zero-init; scan1 re-zeroes after use
__device__ int    g_rowptr[NN + 1];
__device__ int    g_cursor[NN];
__device__ int    g_bsum[SCAN_NB];
__device__ int    g_src[NE];
__device__ int    g_dst[NE];
__device__ int    g_col[NE];
__device__ uint2  g_ylh[NN * 32];      // [NN,128] bf16 gather table — 256 B/row
__device__ float4 g_yr[NN * 32];
__device__ float4 g_res[NN * 32];
__device__ float4 g_h1[NN * 32];
__device__ float4 g_h2[NN * 32];
__device__ float4 g_y2[NN];
__device__ uint4  g_xt4[NN * (KP0 / 4)];       // x tf32, pair-interleaved cols, padded
__device__ uint4  g_h1t4[NN * 32];             // h1 tf32, pair-interleaved cols
__device__ uint4  g_wt4[(3 * W0SZ + 2 * W1SZ) / 4];  // weights tf32, pair-row layout

#define BUF_YR  1
#define BUF_RES 2
#define BUF_H1  3
#define BUF_H2  4
__device__ __forceinline__ float4* buf_ptr(int s) {
    switch (s) {
        case BUF_YR:  return g_yr;
        case BUF_RES: return g_res;
        case BUF_H1:  return g_h1;
        default:      return g_h2;
    }
}

__device__ __forceinline__ int clamp_node(int v) {
    return v < 0 ? 0 : (v >= NN ? NN - 1 : v);
}

// ---------------- tf32 helpers ----------------
__device__ __forceinline__ unsigned f2tf32(float f) {
    unsigned r;
    asm("cvt.rna.tf32.f32 %0, %1;" : "=r"(r) : "f"(f));
    return r;
}
__device__ __forceinline__ void mma_tf32(float c[4], const unsigned a[4],
                                         unsigned b0, unsigned b1) {
    asm("mma.sync.aligned.m16n8k8.row.col.f32.tf32.tf32.f32 "
        "{%0,%1,%2,%3}, {%4,%5,%6,%7}, {%8,%9}, {%0,%1,%2,%3};"
        : "+f"(c[0]), "+f"(c[1]), "+f"(c[2]), "+f"(c[3])
        : "r"(a[0]), "r"(a[1]), "r"(a[2]), "r"(a[3]), "r"(b0), "r"(b1));
}

// pair-interleave: stored position within 8-group for source column k
// stored p = 2*(k&3) + ((k>>2)&1); inverse: k = (p>>1) + 4*(p&1)
__device__ __forceinline__ int perm_src_k(int p) {
    return ((p & 7) >> 1) + 4 * (p & 1) + (p & ~7);
}

// ---------------- edge conversion + inline dtype detect + fused degree histogram ------
__global__ void e_cvt_hist(const void* __restrict__ ei) {
    __shared__ int sh_is64;
    if (threadIdx.x == 0) {
        const int* w = (const int*)ei;
        int all_zero = 1;
        for (int t = 0; t < 32; t++) {
            if (w[2 * t + 1] != 0) { all_zero = 0; break; }
        }
        sh_is64 = all_zero;
    }
    __syncthreads();
    int is64 = sh_is64;
    int i = blockIdx.x * blockDim.x + threadIdx.x;
    if (i < NE) {
        int s, d;
        if (is64) {
            s = (int)((const long long*)ei)[i];
            d = (int)((const long long*)ei)[NE + i];
        } else {
            s = ((const int*)ei)[i];
            d = ((const int*)ei)[NE + i];
        }
        s = clamp_node(s);
        d = clamp_node(d);
        g_src[i] = s;
        g_dst[i] = d;
        atomicAdd(&g_deg[d], 1);
    }
}

// ---------------- CSR scan ----------------
__global__ void k_scan1() {
    __shared__ int sm[256];
    int b = blockIdx.x, t = threadIdx.x;
    int i = b * 256 + t;
    int v = (i < NN) ? g_deg[i] : 0;
    if (i < NN) g_deg[i] = 0;
    sm[t] = v;
    __syncthreads();
    for (int off = 1; off < 256; off <<= 1) {
        int u = (t >= off) ? sm[t - off] : 0;
        __syncthreads();
        sm[t] += u;
        __syncthreads();
    }
    if (i < NN) g_rowptr[i] = sm[t] - v;
    if (t == 255) g_bsum[b] = sm[255];
}

__global__ void k_scan23() {
    __shared__ int sm[256];
    int t = threadIdx.x;
    int b = blockIdx.x;
    int v = (t < SCAN_NB) ? g_bsum[t] : 0;
    sm[t] = v;
    __syncthreads();
    for (int off = 1; off < 256; off <<= 1) {
        int u = (t >= off) ? sm[t - off] : 0;
        __syncthreads();
        sm[t] += u;
        __syncthreads();
    }
    __shared__ int sh_boff;
    if (t == 0) sh_boff = sm[b] - g_bsum[b];
    __syncthreads();
    int boff = sh_boff;
    int i = b * 256 + t;
    if (i < NN) {
        int r = g_rowptr[i] + boff;
        g_rowptr[i] = r;
        g_cursor[i] = r;
    }
    if (i == 0) g_rowptr[NN] = NE;
}

__global__ void k_scatter() {
    int i = blockIdx.x * blockDim.x + threadIdx.x;
    if (i < NE) {
        int pos = atomicAdd(&g_cursor[g_dst[i]], 1);
        if (pos >= 0 && pos < NE) g_col[pos] = g_src[i];
    }
}

// ---------------- x -> padded tf32 table (pair-interleaved columns) ----------------
__global__ void k_xcvt(const float* __restrict__ x) {
    unsigned* xt = reinterpret_cast<unsigned*>(g_xt4);
    int idx = blockIdx.x * blockDim.x + threadIdx.x;
    if (idx < NN * KP0) {
        int row = idx / KP0;
        int p = idx - row * KP0;
        int k = perm_src_k(p);
        unsigned v = 0;
        if (k < IN_DIM) v = f2tf32(x[row * IN_DIM + k]);
        xt[idx] = v;
    }
}

// ---------------- weight transpose -> tf32 pair-row layout ----------------
// per weight: uint2 index u covers (pair-row r, col n): r = u/128, n = u%128;
// k_lo = (r/8)*16 + ((r&7)/4)*8 + (r&3); pair = (W[k_lo][n], W[k_lo+4][n])
__global__ void k_transpose_all(
    const float* __restrict__ Wl0, const float* __restrict__ Wr0,
    const float* __restrict__ Wres0,
    const float* __restrict__ Wl1, const float* __restrict__ Wr1)
{
    unsigned* wt = reinterpret_cast<unsigned*>(g_wt4);
    int i = blockIdx.x * blockDim.x + threadIdx.x;   // word index
    int total0 = 3 * W0SZ;
    if (i < total0 + 2 * W1SZ) {
        const float* W;
        int j, kdim;
        if (i < total0) {
            int seg = i / W0SZ;
            j = i - seg * W0SZ;
            W = (seg == 0) ? Wl0 : (seg == 1) ? Wr0 : Wres0;
            kdim = IN_DIM;
        } else {
            int j2 = i - total0;
            int seg = j2 / W1SZ;
            j = j2 - seg * W1SZ;
            W = seg ? Wr1 : Wl1;
            kdim = HID;
        }
        int sel = j & 1;
        int u = j >> 1;
        int n = u & 127;
        int r = u >> 7;
        int k = (r >> 3) * 16 + ((r & 7) >> 2) * 8 + (r & 3) + (sel ? 4 : 0);
        unsigned v = 0;
        if (k < kdim) v = f2tf32(W[n * kdim + k]);
        wt[i] = v;
    }
}

// ---------------- tf32 tensor-core GEMM: cp.async + LDS.64 fragment loads ------------
#define AS_ST 24                  // A smem row stride (words); banks 24g+2t distinct
#define AS_WORDS (128 * AS_ST)    // 3072 words per buffer
#define B_PR_ST 132               // B pair-row stride (uint2); banks 8t+2g distinct
#define B_UINT2 (8 * B_PR_ST)     // 1056 uint2 per buffer

__global__ __launch_bounds__(256, 2) void k_gemm_tc(
    int a_src,                 // 0 = g_xt4 (KP=176), 1 = g_h1t4 (KP=128)
    int m_base,
    int woff0, int woff1, int woff2,
    int osel1, int osel2,
    const float* __restrict__ bias,   // applied only for blockIdx.y == 1
    int M)
{
    __shared__ __align__(16) unsigned As[2 * AS_WORDS];
    __shared__ __align__(16) uint2    Bs[2 * B_UINT2];

    int yb = blockIdx.y;
    int woff = (yb == 0) ? woff0 : (yb == 1) ? woff1 : woff2;
    const float* bp = (yb == 1) ? bias : nullptr;

    const unsigned* AT = a_src ? reinterpret_cast<const unsigned*>(g_h1t4)
                               : reinterpret_cast<const unsigned*>(g_xt4);
    int KP = a_src ? HID : KP0;
    const uint2* Wt2 = reinterpret_cast<const uint2*>(
        reinterpret_cast<const unsigned*>(g_wt4) + woff);

    int tid = threadIdx.x;
    int lane = tid & 31, wid = tid >> 5;
    int wr = wid & 3, wc = wid >> 2;
    int m0 = m_base + blockIdx.x * 128;
    int gq = lane >> 2, tq = lane & 3;

    unsigned as_u32 = (unsigned)__cvta_generic_to_shared(As);
    unsigned bs_u32 = (unsigned)__cvta_generic_to_shared(Bs);

    // per-thread cp.async descriptors (kt-invariant)
    int arow[2], akg[2], avalid[2];
    int bpr[2], bnn[2];
#pragma unroll
    for (int i = 0; i < 2; i++) {
        int c = tid + i * 256;
        arow[i] = c >> 2;  akg[i] = (c & 3) * 4;
        avalid[i] = (m0 + arow[i]) < M;
        bpr[i] = c >> 6;   bnn[i] = (c & 63) * 2;
    }

    auto stage = [&](int kt, int buf) {
#pragma unroll
        for (int i = 0; i < 2; i++) {
            unsigned dst = as_u32 + (buf * AS_WORDS + arow[i] * AS_ST + akg[i]) * 4u;
            size_t off = avalid[i] ? ((size_t)(m0 + arow[i]) * KP + (kt << 4) + akg[i]) : 0;
            int sz = avalid[i] ? 16 : 0;
            asm volatile("cp.async.cg.shared.global [%0], [%1], 16, %2;"
                         :: "r"(dst), "l"(AT + off), "r"(sz));
        }
#pragma unroll
        for (int i = 0; i < 2; i++) {
            unsigned dst = bs_u32 + (buf * B_UINT2 + bpr[i] * B_PR_ST + bnn[i]) * 8u;
            asm volatile("cp.async.cg.shared.global [%0], [%1], 16;"
                         :: "r"(dst), "l"(Wt2 + (size_t)((kt << 3) + bpr[i]) * 128 + bnn[i]));
        }
        asm volatile("cp.async.commit_group;");
    };

    float acc[2][8][4];
#pragma unroll
    for (int mt = 0; mt < 2; mt++)
#pragma unroll
        for (int ct = 0; ct < 8; ct++)
#pragma unroll
            for (int j = 0; j < 4; j++) acc[mt][ct][j] = 0.f;

    int KT = KP >> 4;
    stage(0, 0);
    for (int kt = 0; kt < KT; kt++) {
        int buf = kt & 1;
        if (kt + 1 < KT) {
            stage(kt + 1, buf ^ 1);
            asm volatile("cp.async.wait_group 1;");
        } else {
            asm volatile("cp.async.wait_group 0;");
        }
        __syncthreads();
        const unsigned* Ab = As + buf * AS_WORDS;
        const uint2* Bb = Bs + buf * B_UINT2;
#pragma unroll
        for (int ks8 = 0; ks8 < 2; ks8++) {
            unsigned af[2][4];
#pragma unroll
            for (int mt = 0; mt < 2; mt++) {
                int mb = wr * 32 + mt * 16;
                uint2 p0 = *(const uint2*)&Ab[(mb + gq) * AS_ST + ks8 * 8 + 2 * tq];
                uint2 p1 = *(const uint2*)&Ab[(mb + gq + 8) * AS_ST + ks8 * 8 + 2 * tq];
                af[mt][0] = p0.x;   // (row gq,   col k)
                af[mt][1] = p1.x;   // (row gq+8, col k)
                af[mt][2] = p0.y;   // (row gq,   col k+4)
                af[mt][3] = p1.y;   // (row gq+8, col k+4)
            }
            const uint2* Brow = Bb + (ks8 * 4 + tq) * B_PR_ST;
#pragma unroll
            for (int ct = 0; ct < 8; ct++) {
                int nb = wc * 64 + ct * 8;
                uint2 b = Brow[nb + gq];
                mma_tf32(acc[0][ct], af[0], b.x, b.y);
                mma_tf32(acc[1][ct], af[1], b.x, b.y);
            }
        }
        __syncthreads();
    }

    if (yb == 0) {
        unsigned* ylh = reinterpret_cast<unsigned*>(g_ylh);
#pragma unroll
        for (int mt = 0; mt < 2; mt++) {
            int r0 = m0 + wr * 32 + mt * 16 + gq;
#pragma unroll
            for (int ct = 0; ct < 8; ct++) {
                int n = wc * 64 + ct * 8 + tq * 2;
                if (r0 < M) {
                    __nv_bfloat162 h = __floats2bfloat162_rn(acc[mt][ct][0], acc[mt][ct][1]);
                    ylh[r0 * 64 + (n >> 1)] = *reinterpret_cast<unsigned*>(&h);
                }
                if (r0 + 8 < M) {
                    __nv_bfloat162 h = __floats2bfloat162_rn(acc[mt][ct][2], acc[mt][ct][3]);
                    ylh[(r0 + 8) * 64 + (n >> 1)] = *reinterpret_cast<unsigned*>(&h);
                }
            }
        }
    } else {
        int osel = (yb == 1) ? osel1 : osel2;
        float* C = reinterpret_cast<float*>(buf_ptr(osel));
#pragma unroll
        for (int mt = 0; mt < 2; mt++) {
            int r0 = m0 + wr * 32 + mt * 16 + gq;
#pragma unroll
            for (int ct = 0; ct < 8; ct++) {
                int n = wc * 64 + ct * 8 + tq * 2;
                float b0v = 0.f, b1v = 0.f;
                if (bp != nullptr) { b0v = bp[n]; b1v = bp[n + 1]; }
                if (r0 < M) {
                    float2 o = make_float2(acc[mt][ct][0] + b0v, acc[mt][ct][1] + b1v);
                    *(float2*)&C[(size_t)r0 * 128 + n] = o;
                }
                if (r0 + 8 < M) {
                    float2 o = make_float2(acc[mt][ct][2] + b0v, acc[mt][ct][3] + b1v);
                    *(float2*)&C[(size_t)(r0 + 8) * 128 + n] = o;
                }
            }
        }
    }
}

// ---------------- aggregation (bf16 gather) + BN + ReLU + residual (+ fused out) ------
__global__ __launch_bounds__(256) void k_agg(
    int n0, int n1,
    int res_sel, int out_sel, int write_t,
    const float* __restrict__ bn_g, const float* __restrict__ bn_b,
    const float* __restrict__ bn_m, const float* __restrict__ bn_v,
    int do_out,
    const float* __restrict__ Wl2, const float* __restrict__ Wr2,
    const float* __restrict__ bl2)
{
    const uint2*  __restrict__ ylh = g_ylh;
    const float4* __restrict__ yr  = g_yr;
    const float4* __restrict__ res = buf_ptr(res_sel);
    float4* __restrict__ out       = buf_ptr(out_sel);
    const int* __restrict__ col    = g_col;

    int w = n0 + ((blockIdx.x * blockDim.x + threadIdx.x) >> 5);
    int lane = threadIdx.x & 31;
    if (w >= n1) return;
    int s0 = g_rowptr[w], s1 = g_rowptr[w + 1];

    float ax = 0.f, ay = 0.f, az = 0.f, aw = 0.f;
    int e = s0;
    for (; e + 7 < s1; e += 8) {
        uint2 p[8];
#pragma unroll
        for (int u = 0; u < 8; u++) {
            int s = clamp_node(col[e + u]);
            p[u] = ylh[s * 32 + lane];
        }
#pragma unroll
        for (int u = 0; u < 8; u++) {
            float2 f0 = __bfloat1622float2(*reinterpret_cast<__nv_bfloat162*>(&p[u].x));
            float2 f1 = __bfloat1622float2(*reinterpret_cast<__nv_bfloat162*>(&p[u].y));
            ax += f0.x; ay += f0.y; az += f1.x; aw += f1.y;
        }
    }
    for (; e < s1; e++) {
        int s = clamp_node(col[e]);
        uint2 p = ylh[s * 32 + lane];
        float2 f0 = __bfloat1622float2(*reinterpret_cast<__nv_bfloat162*>(&p.x));
        float2 f1 = __bfloat1622float2(*reinterpret_cast<__nv_bfloat162*>(&p.y));
        ax += f0.x; ay += f0.y; az += f1.x; aw += f1.y;
    }

    int deg = s1 - s0;
    float inv = 1.f / (float)(deg > 1 ? deg : 1);
    float4 r = yr[w * 32 + lane];
    int f = lane * 4;
    float gx = bn_g[f], gy = bn_g[f + 1], gz = bn_g[f + 2], gw = bn_g[f + 3];
    float bx = bn_b[f], by = bn_b[f + 1], bz = bn_b[f + 2], bw = bn_b[f + 3];
    float mx = bn_m[f], my = bn_m[f + 1], mz = bn_m[f + 2], mw = bn_m[f + 3];
    float qx = bn_v[f], qy = bn_v[f + 1], qz = bn_v[f + 2], qw = bn_v[f + 3];
    float4 rr = res[w * 32 + lane];

    float sx = gx * rsqrtf(qx + BN_EPS);
    float sy = gy * rsqrtf(qy + BN_EPS);
    float sz = gz * rsqrtf(qz + BN_EPS);
    float sw = gw * rsqrtf(qw + BN_EPS);

    float vx = (ax * inv + r.x - mx) * sx + bx;
    float vy = (ay * inv + r.y - my) * sy + by;
    float vz = (az * inv + r.z - mz) * sz + bz;
    float vw = (aw * inv + r.w - mw) * sw + bw;
    vx = fmaxf(vx, 0.f) + rr.x;
    vy = fmaxf(vy, 0.f) + rr.y;
    vz = fmaxf(vz, 0.f) + rr.z;
    vw = fmaxf(vw, 0.f) + rr.w;

    out[w * 32 + lane] = make_float4(vx, vy, vz, vw);

    if (write_t) {
        // pair-interleaved tf32 store: stored idx = 8*(k>>3) + 2*(k&3) + ((k>>2)&1)
        unsigned* ht = reinterpret_cast<unsigned*>(g_h1t4);
        int base = w * HID + 8 * (lane >> 1) + (lane & 1);
        ht[base + 0] = f2tf32(vx);
        ht[base + 2] = f2tf32(vy);
        ht[base + 4] = f2tf32(vz);
        ht[base + 6] = f2tf32(vw);
    }

    if (do_out) {
        float a0 = Wl2[f], a1 = Wl2[f + 1], a2 = Wl2[f + 2], a3 = Wl2[f + 3];
        float b0 = Wl2[128 + f], b1 = Wl2[128 + f + 1], b2 = Wl2[128 + f + 2], b3 = Wl2[128 + f + 3];
        float c0 = Wr2[f], c1 = Wr2[f + 1], c2 = Wr2[f + 2], c3 = Wr2[f + 3];
        float e0 = Wr2[128 + f], e1 = Wr2[128 + f + 1], e2 = Wr2[128 + f + 2], e3 = Wr2[128 + f + 3];
        float d0 = vx * a0 + vy * a1 + vz * a2 + vw * a3;
        float d1 = vx * b0 + vy * b1 + vz * b2 + vw * b3;
        float d2 = vx * c0 + vy * c1 + vz * c2 + vw * c3;
        float d3 = vx * e0 + vy * e1 + vz * e2 + vw * e3;
#pragma unroll
        for (int off = 16; off; off >>= 1) {
            d0 += __shfl_xor_sync(0xffffffffu, d0, off);
            d1 += __shfl_xor_sync(0xffffffffu, d1, off);
            d2 += __shfl_xor_sync(0xffffffffu, d2, off);
            d3 += __shfl_xor_sync(0xffffffffu, d3, off);
        }
        if (lane == 0) {
            g_y2[w] = make_float4(d0, d1, d2 + bl2[0], d3 + bl2[1]);
        }
    }
}

// ---------------- final: aggregate 2-wide logits + root term ----------------
__global__ void k_final(float* __restrict__ out)
{
    int i = blockIdx.x * blockDim.x + threadIdx.x;
    if (i >= NN) return;
    int s0 = g_rowptr[i], s1 = g_rowptr[i + 1];
    float a0 = 0.f, a1 = 0.f;
    int e = s0;
    for (; e + 3 < s1; e += 4) {
        float4 v0 = g_y2[clamp_node(g_col[e])];
        float4 v1 = g_y2[clamp_node(g_col[e + 1])];
        float4 v2 = g_y2[clamp_node(g_col[e + 2])];
        float4 v3 = g_y2[clamp_node(g_col[e + 3])];
        a0 += v0.x + v1.x + v2.x + v3.x;
        a1 += v0.y + v1.y + v2.y + v3.y;
    }
    for (; e < s1; e++) {
        float4 v = g_y2[clamp_node(g_col[e])];
        a0 += v.x;
        a1 += v.y;
    }
    int deg = s1 - s0;
    float inv = 1.f / (float)(deg > 1 ? deg : 1);
    float4 self = g_y2[i];
    out[2 * i + 0] = a0 * inv + self.z;
    out[2 * i + 1] = a1 * inv + self.w;
}

// ---------------- launch ----------------
extern "C" void kernel_launch(void* const* d_in, const int* in_sizes, int n_in,
                              void* d_out, int out_size)
{
    const float* x     = (const float*)d_in[0];
    const void*  ei    = (const void*)d_in[1];
    const float* Wl0   = (const float*)d_in[2];
    const float* bl0   = (const float*)d_in[3];
    const float* Wr0   = (const float*)d_in[4];
    const float* Wl1   = (const float*)d_in[5];
    const float* bl1   = (const float*)d_in[6];
    const float* Wr1   = (const float*)d_in[7];
    const float* Wl2   = (const float*)d_in[8];
    const float* bl2   = (const float*)d_in[9];
    const float* Wr2   = (const float*)d_in[10];
    const float* Wres0 = (const float*)d_in[11];
    const float* bn0_g = (const float*)d_in[12];
    const float* bn0_b = (const float*)d_in[13];
    const float* bn0_m = (const float*)d_in[14];
    const float* bn0_v = (const float*)d_in[15];
    const float* bn1_g = (const float*)d_in[16];
    const float* bn1_b = (const float*)d_in[17];
    const float* bn1_m = (const float*)d_in[18];
    const float* bn1_v = (const float*)d_in[19];

    const int off0l = 0;
    const int off0r = W0SZ;
    const int off0s = 2 * W0SZ;
    const int off1l = 3 * W0SZ;
    const int off1r = 3 * W0SZ + W1SZ;

    cudaStream_t s2;
    cudaStreamCreateWithFlags(&s2, cudaStreamNonBlocking);
    cudaEvent_t evFork, evDense, evCSR, evHalf1;
    cudaEventCreateWithFlags(&evFork,  cudaEventDisableTiming);
    cudaEventCreateWithFlags(&evDense, cudaEventDisableTiming);
    cudaEventCreateWithFlags(&evCSR,   cudaEventDisableTiming);
    cudaEventCreateWithFlags(&evHalf1, cudaEventDisableTiming);

    // fork
    cudaEventRecord(evFork, 0);
    cudaStreamWaitEvent(s2, evFork, 0);

    int gx_all = (NN + 127) / 128;
    int ttotal = 3 * W0SZ + 2 * W1SZ;
    int xtotal = NN * KP0;

    // enqueue order keeps gemm0 as host-launch #4 (ncu window)
    e_cvt_hist<<<(NE + 255) / 256, 256>>>(ei);                                        // #1 s0
    k_xcvt<<<(xtotal + 255) / 256, 256, 0, s2>>>(x);                                  // #2 s2
    k_transpose_all<<<(ttotal + 255) / 256, 256, 0, s2>>>(Wl0, Wr0, Wres0, Wl1, Wr1); // #3 s2
    k_gemm_tc<<<dim3(gx_all, 3), 256, 0, s2>>>(0, 0, off0l, off0r, off0s,
                                               BUF_YR, BUF_RES, bl0, NN);             // #4 s2
    cudaEventRecord(evDense, s2);
    k_scan1<<<SCAN_NB, 256>>>();                                                      // #5 s0
    k_scan23<<<SCAN_NB, 256>>>();                                                     // #6 s0
    k_scatter<<<(NE + 255) / 256, 256>>>();                                           // #7 s0
    cudaEventRecord(evCSR, 0);

    // cross joins
    cudaStreamWaitEvent(0, evDense, 0);
    cudaStreamWaitEvent(s2, evCSR, 0);

    // ---- pipelined layer-0 agg + layer-1 GEMM, split by node halves ----
    int blk_h0 = (H0 * 32 + 255) / 256;
    int blk_h1 = ((NN - H0) * 32 + 255) / 256;
    int gx_h0 = H0 / 128;
    int gx_h1 = (NN - H0 + 127) / 128;

    k_agg<<<blk_h0, 256>>>(0, H0, BUF_RES, BUF_H1, 1, bn0_g, bn0_b, bn0_m, bn0_v,
                           0, nullptr, nullptr, nullptr);
    k_gemm_tc<<<dim3(gx_h0, 2), 256>>>(1, 0, off1l, off1r, off1r,
                                       BUF_YR, BUF_YR, bl1, NN);
    k_agg<<<blk_h1, 256, 0, s2>>>(H0, NN, BUF_RES, BUF_H1, 1, bn0_g, bn0_b, bn0_m, bn0_v,
                                  0, nullptr, nullptr, nullptr);
    k_gemm_tc<<<dim3(gx_h1, 2), 256, 0, s2>>>(1, H0, off1l, off1r, off1r,
                                              BUF_YR, BUF_YR, bl1, NN);
    cudaEventRecord(evHalf1, s2);
    cudaStreamWaitEvent(0, evHalf1, 0);

    // ---- layer-1 aggregate + fused output layer, then final ----
    int blk_all = (NN * 32 + 255) / 256;
    k_agg<<<blk_all, 256>>>(0, NN, BUF_H1, BUF_H2, 0, bn1_g, bn1_b, bn1_m, bn1_v,
                            1, Wl2, Wr2, bl2);
    k_final<<<(NN + 255) / 256, 256>>>((float*)d_out);
}

// round 15
// speedup vs baseline: 1.0057x; 1.0057x over previous
#include <cuda_runtime.h>
#include <cuda_bf16.h>

#define NN 50000
#define NE 800000
#define IN_DIM 166
#define HID 128
#define BN_EPS 1e-5f
#define SCAN_NB 196   // ceil(NN/256)
#define H0 25088      // node split point (multiple of 128)

#define KP0 176                    // padded K for layer 0
#define W0SZ (KP0 * HID)           // 22528 words per layer-0 weight
#define W1SZ (HID * HID)           // 16384 words per layer-1 weight

// ---------------- scratch ----------------
__device__ int    g_deg[NN];           // statically zero-init; scan1 re-zeroes after use
__device__ int    g_rowptr[NN + 1];
__device__ int    g_cursor[NN];
__device__ int    g_bsum[SCAN_NB];
__device__ int    g_src[NE];
__device__ int    g_dst[NE];
__device__ int    g_col[NE];
__device__ uint2  g_ylh[NN * 32];      // [NN,128] bf16 gather table — 256 B/row
__device__ float4 g_yr[NN * 32];
__device__ float4 g_res[NN * 32];
__device__ float4 g_h1[NN * 32];
__device__ float4 g_h2[NN * 32];
__device__ float4 g_y2[NN];
__device__ uint4  g_xt4[NN * (KP0 / 4)];       // x pre-converted to tf32, padded rows
__device__ uint4  g_h1t4[NN * 32];             // h1 tf32 copy for layer-1 GEMM
__device__ uint4  g_wt4[(3 * W0SZ + 2 * W1SZ) / 4];  // transposed tf32 weights

#define BUF_YR  1
#define BUF_RES 2
#define BUF_H1  3
#define BUF_H2  4
__device__ __forceinline__ float4* buf_ptr(int s) {
    switch (s) {
        case BUF_YR:  return g_yr;
        case BUF_RES: return g_res;
        case BUF_H1:  return g_h1;
        default:      return g_h2;
    }
}

__device__ __forceinline__ int clamp_node(int v) {
    return v < 0 ? 0 : (v >= NN ? NN - 1 : v);
}

// ---------------- tf32 helpers ----------------
__device__ __forceinline__ unsigned f2tf32(float f) {
    unsigned r;
    asm("cvt.rna.tf32.f32 %0, %1;" : "=r"(r) : "f"(f));
    return r;
}
__device__ __forceinline__ void mma_tf32(float c[4], const unsigned a[4],
                                         unsigned b0, unsigned b1) {
    asm("mma.sync.aligned.m16n8k8.row.col.f32.tf32.tf32.f32 "
        "{%0,%1,%2,%3}, {%4,%5,%6,%7}, {%8,%9}, {%0,%1,%2,%3};"
        : "+f"(c[0]), "+f"(c[1]), "+f"(c[2]), "+f"(c[3])
        : "r"(a[0]), "r"(a[1]), "r"(a[2]), "r"(a[3]), "r"(b0), "r"(b1));
}

// ---------------- edge conversion + inline dtype detect + fused degree histogram ------
__global__ void e_cvt_hist(const void* __restrict__ ei) {
    __shared__ int sh_is64;
    if (threadIdx.x == 0) {
        const int* w = (const int*)ei;
        int all_zero = 1;
        for (int t = 0; t < 32; t++) {
            if (w[2 * t + 1] != 0) { all_zero = 0; break; }
        }
        sh_is64 = all_zero;
    }
    __syncthreads();
    int is64 = sh_is64;
    int i = blockIdx.x * blockDim.x + threadIdx.x;
    if (i < NE) {
        int s, d;
        if (is64) {
            s = (int)((const long long*)ei)[i];
            d = (int)((const long long*)ei)[NE + i];
        } else {
            s = ((const int*)ei)[i];
            d = ((const int*)ei)[NE + i];
        }
        s = clamp_node(s);
        d = clamp_node(d);
        g_src[i] = s;
        g_dst[i] = d;
        atomicAdd(&g_deg[d], 1);
    }
}

// ---------------- CSR scan ----------------
__global__ void k_scan1() {
    __shared__ int sm[256];
    int b = blockIdx.x, t = threadIdx.x;
    int i = b * 256 + t;
    int v = (i < NN) ? g_deg[i] : 0;
    if (i < NN) g_deg[i] = 0;   // restore zeros for the next replay
    sm[t] = v;
    __syncthreads();
    for (int off = 1; off < 256; off <<= 1) {
        int u = (t >= off) ? sm[t - off] : 0;
        __syncthreads();
        sm[t] += u;
        __syncthreads();
    }
    if (i < NN) g_rowptr[i] = sm[t] - v;
    if (t == 255) g_bsum[b] = sm[255];
}

__global__ void k_scan23() {
    __shared__ int sm[256];
    int t = threadIdx.x;
    int b = blockIdx.x;
    int v = (t < SCAN_NB) ? g_bsum[t] : 0;
    sm[t] = v;
    __syncthreads();
    for (int off = 1; off < 256; off <<= 1) {
        int u = (t >= off) ? sm[t - off] : 0;
        __syncthreads();
        sm[t] += u;
        __syncthreads();
    }
    __shared__ int sh_boff;
    if (t == 0) sh_boff = sm[b] - g_bsum[b];
    __syncthreads();
    int boff = sh_boff;
    int i = b * 256 + t;
    if (i < NN) {
        int r = g_rowptr[i] + boff;
        g_rowptr[i] = r;
        g_cursor[i] = r;
    }
    if (i == 0) g_rowptr[NN] = NE;
}

__global__ void k_scatter() {
    int i = blockIdx.x * blockDim.x + threadIdx.x;
    if (i < NE) {
        int pos = atomicAdd(&g_cursor[g_dst[i]], 1);
        if (pos >= 0 && pos < NE) g_col[pos] = g_src[i];
    }
}

// ---------------- fused prep: x -> tf32 padded table AND weights -> tf32 transposed ---
#define XT_TOTAL (NN * KP0)
#define WT_TOTAL (3 * W0SZ + 2 * W1SZ)

__global__ void k_prep(
    const float* __restrict__ x,
    const float* __restrict__ Wl0, const float* __restrict__ Wr0,
    const float* __restrict__ Wres0,
    const float* __restrict__ Wl1, const float* __restrict__ Wr1)
{
    int i = blockIdx.x * blockDim.x + threadIdx.x;
    if (i < XT_TOTAL) {
        unsigned* xt = reinterpret_cast<unsigned*>(g_xt4);
        int row = i / KP0;
        int k = i - row * KP0;
        unsigned v = 0;
        if (k < IN_DIM) v = f2tf32(x[row * IN_DIM + k]);
        xt[i] = v;
    } else {
        int j = i - XT_TOTAL;
        if (j < WT_TOTAL) {
            unsigned* wt = reinterpret_cast<unsigned*>(g_wt4);
            if (j < 3 * W0SZ) {
                int seg = j / W0SZ;
                int jj = j - seg * W0SZ;
                int k = jj >> 7, n = jj & 127;
                const float* W = (seg == 0) ? Wl0 : (seg == 1) ? Wr0 : Wres0;
                unsigned v = 0;
                if (k < IN_DIM) v = f2tf32(W[n * IN_DIM + k]);
                wt[j] = v;
            } else {
                int j2 = j - 3 * W0SZ;
                int seg = j2 / W1SZ;
                int jj = j2 - seg * W1SZ;
                int k = jj >> 7, n = jj & 127;
                const float* W = seg ? Wr1 : Wl1;
                wt[j] = f2tf32(W[n * HID + k]);
            }
        }
    }
}

// ---------------- tf32 tensor-core GEMM: cp.async, single-sync pipeline --------------
// inputs already tf32 in memory; yb==0 writes bf16 gather table, yb>=1 fp32.
#define AS_ST 20
#define BS_ST 136
#define A_WORDS (128 * AS_ST)   // 2560
#define B_WORDS (16 * BS_ST)    // 2176

__global__ __launch_bounds__(256, 2) void k_gemm_tc(
    int a_src,                 // 0 = g_xt4 (KP=176), 1 = g_h1t4 (KP=128)
    int m_base,
    int woff0, int woff1, int woff2,
    int osel1, int osel2,
    const float* __restrict__ bias,   // applied only for blockIdx.y == 1
    int M)
{
    __shared__ __align__(16) unsigned As[2 * A_WORDS];
    __shared__ __align__(16) unsigned Bs[2 * B_WORDS];

    int yb = blockIdx.y;
    int woff = (yb == 0) ? woff0 : (yb == 1) ? woff1 : woff2;
    const float* bp = (yb == 1) ? bias : nullptr;

    const unsigned* AT = a_src ? reinterpret_cast<const unsigned*>(g_h1t4)
                               : reinterpret_cast<const unsigned*>(g_xt4);
    int KP = a_src ? HID : KP0;
    const unsigned* Wt = reinterpret_cast<const unsigned*>(g_wt4) + woff;

    int tid = threadIdx.x;
    int lane = tid & 31, wid = tid >> 5;
    int wr = wid & 3, wc = wid >> 2;
    int m0 = m_base + blockIdx.x * 128;
    int gq = lane >> 2, tq = lane & 3;

    unsigned as_u32 = (unsigned)__cvta_generic_to_shared(As);
    unsigned bs_u32 = (unsigned)__cvta_generic_to_shared(Bs);

    // per-thread load descriptors (kt-invariant)
    int arow[2], akg[2], avalid[2];
    int brow[2], bng[2];
#pragma unroll
    for (int i = 0; i < 2; i++) {
        int c = tid + i * 256;
        arow[i] = c >> 2;  akg[i] = (c & 3) * 4;
        avalid[i] = (m0 + arow[i]) < M;
        brow[i] = c >> 5;  bng[i] = (c & 31) * 4;
    }

    auto stage = [&](int kt, int buf) {
        int k0 = kt << 4;
#pragma unroll
        for (int i = 0; i < 2; i++) {
            unsigned dst = as_u32 + (buf * A_WORDS + arow[i] * AS_ST + akg[i]) * 4u;
            size_t off = avalid[i] ? ((size_t)(m0 + arow[i]) * KP + k0 + akg[i]) : 0;
            int sz = avalid[i] ? 16 : 0;
            asm volatile("cp.async.cg.shared.global [%0], [%1], 16, %2;"
                         :: "r"(dst), "l"(AT + off), "r"(sz));
        }
#pragma unroll
        for (int i = 0; i < 2; i++) {
            unsigned dst = bs_u32 + (buf * B_WORDS + brow[i] * BS_ST + bng[i]) * 4u;
            asm volatile("cp.async.cg.shared.global [%0], [%1], 16;"
                         :: "r"(dst), "l"(Wt + (size_t)(k0 + brow[i]) * 128 + bng[i]));
        }
        asm volatile("cp.async.commit_group;");
    };

    float acc[2][8][4];
#pragma unroll
    for (int mt = 0; mt < 2; mt++)
#pragma unroll
        for (int ct = 0; ct < 8; ct++)
#pragma unroll
            for (int j = 0; j < 4; j++) acc[mt][ct][j] = 0.f;

    int KT = KP >> 4;
    stage(0, 0);
    for (int kt = 0; kt < KT; kt++) {
        int buf = kt & 1;
        // stage kt is the only pending group; it had a full tile of compute to land
        asm volatile("cp.async.wait_group 0;");
        __syncthreads();   // collective: all threads done reading buf^1 (iter kt-1)
        if (kt + 1 < KT) stage(kt + 1, buf ^ 1);   // safe post-barrier; overlaps compute
        const unsigned* Ab = As + buf * A_WORDS;
        const unsigned* Bb = Bs + buf * B_WORDS;
#pragma unroll
        for (int ks = 0; ks < 16; ks += 8) {
            unsigned af[2][4];
#pragma unroll
            for (int mt = 0; mt < 2; mt++) {
                int mb = wr * 32 + mt * 16;
                af[mt][0] = Ab[(mb + gq) * AS_ST + ks + tq];
                af[mt][1] = Ab[(mb + gq + 8) * AS_ST + ks + tq];
                af[mt][2] = Ab[(mb + gq) * AS_ST + ks + tq + 4];
                af[mt][3] = Ab[(mb + gq + 8) * AS_ST + ks + tq + 4];
            }
#pragma unroll
            for (int ct = 0; ct < 8; ct++) {
                int nb = wc * 64 + ct * 8;
                unsigned b0 = Bb[(ks + tq) * BS_ST + nb + gq];
                unsigned b1 = Bb[(ks + tq + 4) * BS_ST + nb + gq];
                mma_tf32(acc[0][ct], af[0], b0, b1);
                mma_tf32(acc[1][ct], af[1], b0, b1);
            }
        }
    }

    if (yb == 0) {
        unsigned* ylh = reinterpret_cast<unsigned*>(g_ylh);
#pragma unroll
        for (int mt = 0; mt < 2; mt++) {
            int r0 = m0 + wr * 32 + mt * 16 + gq;
#pragma unroll
            for (int ct = 0; ct < 8; ct++) {
                int n = wc * 64 + ct * 8 + tq * 2;
                if (r0 < M) {
                    __nv_bfloat162 h = __floats2bfloat162_rn(acc[mt][ct][0], acc[mt][ct][1]);
                    ylh[r0 * 64 + (n >> 1)] = *reinterpret_cast<unsigned*>(&h);
                }
                if (r0 + 8 < M) {
                    __nv_bfloat162 h = __floats2bfloat162_rn(acc[mt][ct][2], acc[mt][ct][3]);
                    ylh[(r0 + 8) * 64 + (n >> 1)] = *reinterpret_cast<unsigned*>(&h);
                }
            }
        }
    } else {
        int osel = (yb == 1) ? osel1 : osel2;
        float* C = reinterpret_cast<float*>(buf_ptr(osel));
#pragma unroll
        for (int mt = 0; mt < 2; mt++) {
            int r0 = m0 + wr * 32 + mt * 16 + gq;
#pragma unroll
            for (int ct = 0; ct < 8; ct++) {
                int n = wc * 64 + ct * 8 + tq * 2;
                float b0v = 0.f, b1v = 0.f;
                if (bp != nullptr) { b0v = bp[n]; b1v = bp[n + 1]; }
                if (r0 < M) {
                    float2 o = make_float2(acc[mt][ct][0] + b0v, acc[mt][ct][1] + b1v);
                    *(float2*)&C[(size_t)r0 * 128 + n] = o;
                }
                if (r0 + 8 < M) {
                    float2 o = make_float2(acc[mt][ct][2] + b0v, acc[mt][ct][3] + b1v);
                    *(float2*)&C[(size_t)(r0 + 8) * 128 + n] = o;
                }
            }
        }
    }
}

// ---------------- aggregation (bf16 gather) + BN + ReLU + residual (+ fused out) ------
__global__ __launch_bounds__(256) void k_agg(
    int n0, int n1,
    int res_sel, int out_sel, int write_t,
    const float* __restrict__ bn_g, const float* __restrict__ bn_b,
    const float* __restrict__ bn_m, const float* __restrict__ bn_v,
    int do_out,
    const float* __restrict__ Wl2, const float* __restrict__ Wr2,
    const float* __restrict__ bl2)
{
    const uint2*  __restrict__ ylh = g_ylh;
    const float4* __restrict__ yr  = g_yr;
    const float4* __restrict__ res = buf_ptr(res_sel);
    float4* __restrict__ out       = buf_ptr(out_sel);
    const int* __restrict__ col    = g_col;

    int w = n0 + ((blockIdx.x * blockDim.x + threadIdx.x) >> 5);
    int lane = threadIdx.x & 31;
    if (w >= n1) return;
    int s0 = g_rowptr[w], s1 = g_rowptr[w + 1];

    float ax = 0.f, ay = 0.f, az = 0.f, aw = 0.f;
    int e = s0;
    for (; e + 7 < s1; e += 8) {
        uint2 p[8];
#pragma unroll
        for (int u = 0; u < 8; u++) {
            int s = clamp_node(col[e + u]);
            p[u] = ylh[s * 32 + lane];
        }
#pragma unroll
        for (int u = 0; u < 8; u++) {
            float2 f0 = __bfloat1622float2(*reinterpret_cast<__nv_bfloat162*>(&p[u].x));
            float2 f1 = __bfloat1622float2(*reinterpret_cast<__nv_bfloat162*>(&p[u].y));
            ax += f0.x; ay += f0.y; az += f1.x; aw += f1.y;
        }
    }
    for (; e < s1; e++) {
        int s = clamp_node(col[e]);
        uint2 p = ylh[s * 32 + lane];
        float2 f0 = __bfloat1622float2(*reinterpret_cast<__nv_bfloat162*>(&p.x));
        float2 f1 = __bfloat1622float2(*reinterpret_cast<__nv_bfloat162*>(&p.y));
        ax += f0.x; ay += f0.y; az += f1.x; aw += f1.y;
    }

    int deg = s1 - s0;
    float inv = 1.f / (float)(deg > 1 ? deg : 1);
    float4 r = yr[w * 32 + lane];
    int f = lane * 4;
    float gx = bn_g[f], gy = bn_g[f + 1], gz = bn_g[f + 2], gw = bn_g[f + 3];
    float bx = bn_b[f], by = bn_b[f + 1], bz = bn_b[f + 2], bw = bn_b[f + 3];
    float mx = bn_m[f], my = bn_m[f + 1], mz = bn_m[f + 2], mw = bn_m[f + 3];
    float qx = bn_v[f], qy = bn_v[f + 1], qz = bn_v[f + 2], qw = bn_v[f + 3];
    float4 rr = res[w * 32 + lane];

    float sx = gx * rsqrtf(qx + BN_EPS);
    float sy = gy * rsqrtf(qy + BN_EPS);
    float sz = gz * rsqrtf(qz + BN_EPS);
    float sw = gw * rsqrtf(qw + BN_EPS);

    float vx = (ax * inv + r.x - mx) * sx + bx;
    float vy = (ay * inv + r.y - my) * sy + by;
    float vz = (az * inv + r.z - mz) * sz + bz;
    float vw = (aw * inv + r.w - mw) * sw + bw;
    vx = fmaxf(vx, 0.f) + rr.x;
    vy = fmaxf(vy, 0.f) + rr.y;
    vz = fmaxf(vz, 0.f) + rr.z;
    vw = fmaxf(vw, 0.f) + rr.w;

    out[w * 32 + lane] = make_float4(vx, vy, vz, vw);

    if (write_t) {
        uint4 t;
        t.x = f2tf32(vx); t.y = f2tf32(vy); t.z = f2tf32(vz); t.w = f2tf32(vw);
        g_h1t4[w * 32 + lane] = t;
    }

    if (do_out) {
        float a0 = Wl2[f], a1 = Wl2[f + 1], a2 = Wl2[f + 2], a3 = Wl2[f + 3];
        float b0 = Wl2[128 + f], b1 = Wl2[128 + f + 1], b2 = Wl2[128 + f + 2], b3 = Wl2[128 + f + 3];
        float c0 = Wr2[f], c1 = Wr2[f + 1], c2 = Wr2[f + 2], c3 = Wr2[f + 3];
        float e0 = Wr2[128 + f], e1 = Wr2[128 + f + 1], e2 = Wr2[128 + f + 2], e3 = Wr2[128 + f + 3];
        float d0 = vx * a0 + vy * a1 + vz * a2 + vw * a3;
        float d1 = vx * b0 + vy * b1 + vz * b2 + vw * b3;
        float d2 = vx * c0 + vy * c1 + vz * c2 + vw * c3;
        float d3 = vx * e0 + vy * e1 + vz * e2 + vw * e3;
#pragma unroll
        for (int off = 16; off; off >>= 1) {
            d0 += __shfl_xor_sync(0xffffffffu, d0, off);
            d1 += __shfl_xor_sync(0xffffffffu, d1, off);
            d2 += __shfl_xor_sync(0xffffffffu, d2, off);
            d3 += __shfl_xor_sync(0xffffffffu, d3, off);
        }
        if (lane == 0) {
            g_y2[w] = make_float4(d0, d1, d2 + bl2[0], d3 + bl2[1]);
        }
    }
}

// ---------------- final: aggregate 2-wide logits + root term ----------------
__global__ void k_final(float* __restrict__ out)
{
    int i = blockIdx.x * blockDim.x + threadIdx.x;
    if (i >= NN) return;
    int s0 = g_rowptr[i], s1 = g_rowptr[i + 1];
    float a0 = 0.f, a1 = 0.f;
    int e = s0;
    for (; e + 3 < s1; e += 4) {
        float4 v0 = g_y2[clamp_node(g_col[e])];
        float4 v1 = g_y2[clamp_node(g_col[e + 1])];
        float4 v2 = g_y2[clamp_node(g_col[e + 2])];
        float4 v3 = g_y2[clamp_node(g_col[e + 3])];
        a0 += v0.x + v1.x + v2.x + v3.x;
        a1 += v0.y + v1.y + v2.y + v3.y;
    }
    for (; e < s1; e++) {
        float4 v = g_y2[clamp_node(g_col[e])];
        a0 += v.x;
        a1 += v.y;
    }
    int deg = s1 - s0;
    float inv = 1.f / (float)(deg > 1 ? deg : 1);
    float4 self = g_y2[i];
    out[2 * i + 0] = a0 * inv + self.z;
    out[2 * i + 1] = a1 * inv + self.w;
}

// ---------------- launch ----------------
extern "C" void kernel_launch(void* const* d_in, const int* in_sizes, int n_in,
                              void* d_out, int out_size)
{
    const float* x     = (const float*)d_in[0];
    const void*  ei    = (const void*)d_in[1];
    const float* Wl0   = (const float*)d_in[2];
    const float* bl0   = (const float*)d_in[3];
    const float* Wr0   = (const float*)d_in[4];
    const float* Wl1   = (const float*)d_in[5];
    const float* bl1   = (const float*)d_in[6];
    const float* Wr1   = (const float*)d_in[7];
    const float* Wl2   = (const float*)d_in[8];
    const float* bl2   = (const float*)d_in[9];
    const float* Wr2   = (const float*)d_in[10];
    const float* Wres0 = (const float*)d_in[11];
    const float* bn0_g = (const float*)d_in[12];
    const float* bn0_b = (const float*)d_in[13];
    const float* bn0_m = (const float*)d_in[14];
    const float* bn0_v = (const float*)d_in[15];
    const float* bn1_g = (const float*)d_in[16];
    const float* bn1_b = (const float*)d_in[17];
    const float* bn1_m = (const float*)d_in[18];
    const float* bn1_v = (const float*)d_in[19];

    const int off0l = 0;
    const int off0r = W0SZ;
    const int off0s = 2 * W0SZ;
    const int off1l = 3 * W0SZ;
    const int off1r = 3 * W0SZ + W1SZ;

    cudaStream_t s2;
    cudaStreamCreateWithFlags(&s2, cudaStreamNonBlocking);
    cudaEvent_t evFork, evDense, evCSR, evHalf1;
    cudaEventCreateWithFlags(&evFork,  cudaEventDisableTiming);
    cudaEventCreateWithFlags(&evDense, cudaEventDisableTiming);
    cudaEventCreateWithFlags(&evCSR,   cudaEventDisableTiming);
    cudaEventCreateWithFlags(&evHalf1, cudaEventDisableTiming);

    // fork
    cudaEventRecord(evFork, 0);
    cudaStreamWaitEvent(s2, evFork, 0);

    int gx_all = (NN + 127) / 128;
    int ptotal = XT_TOTAL + WT_TOTAL;

    // enqueue order keeps gemm0 as host-launch #4 (ncu window)
    e_cvt_hist<<<(NE + 255) / 256, 256>>>(ei);                                        // #1 s0
    k_scan1<<<SCAN_NB, 256>>>();                                                      // #2 s0
    k_prep<<<(ptotal + 255) / 256, 256, 0, s2>>>(x, Wl0, Wr0, Wres0, Wl1, Wr1);       // #3 s2
    k_gemm_tc<<<dim3(gx_all, 3), 256, 0, s2>>>(0, 0, off0l, off0r, off0s,
                                               BUF_YR, BUF_RES, bl0, NN);             // #4 s2
    cudaEventRecord(evDense, s2);
    k_scan23<<<SCAN_NB, 256>>>();                                                     // #5 s0
    k_scatter<<<(NE + 255) / 256, 256>>>();                                           // #6 s0
    cudaEventRecord(evCSR, 0);

    // cross joins
    cudaStreamWaitEvent(0, evDense, 0);
    cudaStreamWaitEvent(s2, evCSR, 0);

    // ---- pipelined layer-0 agg + layer-1 GEMM, split by node halves ----
    int blk_h0 = (H0 * 32 + 255) / 256;
    int blk_h1 = ((NN - H0) * 32 + 255) / 256;
    int gx_h0 = H0 / 128;
    int gx_h1 = (NN - H0 + 127) / 128;

    k_agg<<<blk_h0, 256>>>(0, H0, BUF_RES, BUF_H1, 1, bn0_g, bn0_b, bn0_m, bn0_v,
                           0, nullptr, nullptr, nullptr);
    k_gemm_tc<<<dim3(gx_h0, 2), 256>>>(1, 0, off1l, off1r, off1r,
                                       BUF_YR, BUF_YR, bl1, NN);
    k_agg<<<blk_h1, 256, 0, s2>>>(H0, NN, BUF_RES, BUF_H1, 1, bn0_g, bn0_b, bn0_m, bn0_v,
                                  0, nullptr, nullptr, nullptr);
    k_gemm_tc<<<dim3(gx_h1, 2), 256, 0, s2>>>(1, H0, off1l, off1r, off1r,
                                              BUF_YR, BUF_YR, bl1, NN);
    cudaEventRecord(evHalf1, s2);
    cudaStreamWaitEvent(0, evHalf1, 0);

    // ---- layer-1 aggregate + fused output layer, then final ----
    int blk_all = (NN * 32 + 255) / 256;
    k_agg<<<blk_all, 256>>>(0, NN, BUF_H1, BUF_H2, 0, bn1_g, bn1_b, bn1_m, bn1_v,
                            1, Wl2, Wr2, bl2);
    k_final<<<(NN + 255) / 256, 256>>>((float*)d_out);
}

// round 16
// speedup vs baseline: 1.0257x; 1.0199x over previous
#include <cuda_runtime.h>
#include <cuda_bf16.h>

#define NN 50000
#define NE 800000
#define IN_DIM 166
#define HID 128
#define BN_EPS 1e-5f
#define SCAN_NB 196   // ceil(NN/256)
#define H0 25088      // node split point (multiple of 128)

#define KP0 176                    // padded K for layer 0
#define W0SZ (KP0 * HID)           // 22528 words per layer-0 weight
#define W1SZ (HID * HID)           // 16384 words per layer-1 weight

// ---------------- scratch ----------------
__device__ int    g_deg[NN];           // statically zero-init; scan1 re-zeroes after use
__device__ int    g_rowptr[NN + 1];
__device__ int    g_cursor[NN];
__device__ int    g_bsum[SCAN_NB];
__device__ int    g_src[NE];
__device__ int    g_dst[NE];
__device__ int    g_col[NE];
__device__ uint2  g_ylh[NN * 32];      // [NN,128] bf16 gather table — 256 B/row
__device__ float4 g_yr[NN * 32];
__device__ float4 g_res[NN * 32];
__device__ float4 g_y2[NN];
__device__ uint4  g_xt4[NN * (KP0 / 4)];       // x pre-converted to tf32, padded rows
__device__ uint4  g_h1t4[NN * 32];             // h1 in tf32 (A for gemm1 AND residual)
__device__ uint4  g_wt4[(3 * W0SZ + 2 * W1SZ) / 4];  // transposed tf32 weights

#define BUF_YR  1
#define BUF_RES 2
#define RES_H1T 5    // residual read from g_h1t4 (tf32 bit-pattern = valid fp32)
__device__ __forceinline__ float4* buf_ptr(int s) {
    return (s == BUF_YR) ? g_yr : g_res;
}

__device__ __forceinline__ int clamp_node(int v) {
    return v < 0 ? 0 : (v >= NN ? NN - 1 : v);
}

// ---------------- tf32 helpers ----------------
__device__ __forceinline__ unsigned f2tf32(float f) {
    unsigned r;
    asm("cvt.rna.tf32.f32 %0, %1;" : "=r"(r) : "f"(f));
    return r;
}
__device__ __forceinline__ void mma_tf32(float c[4], const unsigned a[4],
                                         unsigned b0, unsigned b1) {
    asm("mma.sync.aligned.m16n8k8.row.col.f32.tf32.tf32.f32 "
        "{%0,%1,%2,%3}, {%4,%5,%6,%7}, {%8,%9}, {%0,%1,%2,%3};"
        : "+f"(c[0]), "+f"(c[1]), "+f"(c[2]), "+f"(c[3])
        : "r"(a[0]), "r"(a[1]), "r"(a[2]), "r"(a[3]), "r"(b0), "r"(b1));
}

// ---------------- edge conversion + inline dtype detect + fused degree histogram ------
__global__ void e_cvt_hist(const void* __restrict__ ei) {
    __shared__ int sh_is64;
    if (threadIdx.x == 0) {
        const int* w = (const int*)ei;
        int all_zero = 1;
        for (int t = 0; t < 32; t++) {
            if (w[2 * t + 1] != 0) { all_zero = 0; break; }
        }
        sh_is64 = all_zero;
    }
    __syncthreads();
    int is64 = sh_is64;
    int i = blockIdx.x * blockDim.x + threadIdx.x;
    if (i < NE) {
        int s, d;
        if (is64) {
            s = (int)((const long long*)ei)[i];
            d = (int)((const long long*)ei)[NE + i];
        } else {
            s = ((const int*)ei)[i];
            d = ((const int*)ei)[NE + i];
        }
        s = clamp_node(s);
        d = clamp_node(d);
        g_src[i] = s;
        g_dst[i] = d;
        atomicAdd(&g_deg[d], 1);
    }
}

// ---------------- CSR scan ----------------
__global__ void k_scan1() {
    __shared__ int sm[256];
    int b = blockIdx.x, t = threadIdx.x;
    int i = b * 256 + t;
    int v = (i < NN) ? g_deg[i] : 0;
    if (i < NN) g_deg[i] = 0;   // restore zeros for the next replay
    sm[t] = v;
    __syncthreads();
    for (int off = 1; off < 256; off <<= 1) {
        int u = (t >= off) ? sm[t - off] : 0;
        __syncthreads();
        sm[t] += u;
        __syncthreads();
    }
    if (i < NN) g_rowptr[i] = sm[t] - v;
    if (t == 255) g_bsum[b] = sm[255];
}

__global__ void k_scan23() {
    __shared__ int sm[256];
    int t = threadIdx.x;
    int b = blockIdx.x;
    int v = (t < SCAN_NB) ? g_bsum[t] : 0;
    sm[t] = v;
    __syncthreads();
    for (int off = 1; off < 256; off <<= 1) {
        int u = (t >= off) ? sm[t - off] : 0;
        __syncthreads();
        sm[t] += u;
        __syncthreads();
    }
    __shared__ int sh_boff;
    if (t == 0) sh_boff = sm[b] - g_bsum[b];
    __syncthreads();
    int boff = sh_boff;
    int i = b * 256 + t;
    if (i < NN) {
        int r = g_rowptr[i] + boff;
        g_rowptr[i] = r;
        g_cursor[i] = r;
    }
    if (i == 0) g_rowptr[NN] = NE;
}

__global__ void k_scatter() {
    int i = blockIdx.x * blockDim.x + threadIdx.x;
    if (i < NE) {
        int pos = atomicAdd(&g_cursor[g_dst[i]], 1);
        if (pos >= 0 && pos < NE) g_col[pos] = g_src[i];
    }
}

// ---------------- fused prep: x -> tf32 padded table AND weights -> tf32 transposed ---
#define XT_TOTAL (NN * KP0)
#define WT_TOTAL (3 * W0SZ + 2 * W1SZ)

__global__ void k_prep(
    const float* __restrict__ x,
    const float* __restrict__ Wl0, const float* __restrict__ Wr0,
    const float* __restrict__ Wres0,
    const float* __restrict__ Wl1, const float* __restrict__ Wr1)
{
    int i = blockIdx.x * blockDim.x + threadIdx.x;
    if (i < XT_TOTAL) {
        unsigned* xt = reinterpret_cast<unsigned*>(g_xt4);
        int row = i / KP0;
        int k = i - row * KP0;
        unsigned v = 0;
        if (k < IN_DIM) v = f2tf32(x[row * IN_DIM + k]);
        xt[i] = v;
    } else {
        int j = i - XT_TOTAL;
        if (j < WT_TOTAL) {
            unsigned* wt = reinterpret_cast<unsigned*>(g_wt4);
            if (j < 3 * W0SZ) {
                int seg = j / W0SZ;
                int jj = j - seg * W0SZ;
                int k = jj >> 7, n = jj & 127;
                const float* W = (seg == 0) ? Wl0 : (seg == 1) ? Wr0 : Wres0;
                unsigned v = 0;
                if (k < IN_DIM) v = f2tf32(W[n * IN_DIM + k]);
                wt[j] = v;
            } else {
                int j2 = j - 3 * W0SZ;
                int seg = j2 / W1SZ;
                int jj = j2 - seg * W1SZ;
                int k = jj >> 7, n = jj & 127;
                const float* W = seg ? Wr1 : Wl1;
                wt[j] = f2tf32(W[n * HID + k]);
            }
        }
    }
}

// ---------------- tf32 tensor-core GEMM: cp.async, single-sync pipeline --------------
#define AS_ST 20
#define BS_ST 136
#define A_WORDS (128 * AS_ST)   // 2560
#define B_WORDS (16 * BS_ST)    // 2176

__global__ __launch_bounds__(256, 2) void k_gemm_tc(
    int a_src,                 // 0 = g_xt4 (KP=176), 1 = g_h1t4 (KP=128)
    int m_base,
    int woff0, int woff1, int woff2,
    int osel1, int osel2,
    const float* __restrict__ bias,   // applied only for blockIdx.y == 1
    int M)
{
    __shared__ __align__(16) unsigned As[2 * A_WORDS];
    __shared__ __align__(16) unsigned Bs[2 * B_WORDS];

    int yb = blockIdx.y;
    int woff = (yb == 0) ? woff0 : (yb == 1) ? woff1 : woff2;
    const float* bp = (yb == 1) ? bias : nullptr;

    const unsigned* AT = a_src ? reinterpret_cast<const unsigned*>(g_h1t4)
                               : reinterpret_cast<const unsigned*>(g_xt4);
    int KP = a_src ? HID : KP0;
    const unsigned* Wt = reinterpret_cast<const unsigned*>(g_wt4) + woff;

    int tid = threadIdx.x;
    int lane = tid & 31, wid = tid >> 5;
    int wr = wid & 3, wc = wid >> 2;
    int m0 = m_base + blockIdx.x * 128;
    int gq = lane >> 2, tq = lane & 3;

    unsigned as_u32 = (unsigned)__cvta_generic_to_shared(As);
    unsigned bs_u32 = (unsigned)__cvta_generic_to_shared(Bs);

    int arow[2], akg[2], avalid[2];
    int brow[2], bng[2];
#pragma unroll
    for (int i = 0; i < 2; i++) {
        int c = tid + i * 256;
        arow[i] = c >> 2;  akg[i] = (c & 3) * 4;
        avalid[i] = (m0 + arow[i]) < M;
        brow[i] = c >> 5;  bng[i] = (c & 31) * 4;
    }

    auto stage = [&](int kt, int buf) {
        int k0 = kt << 4;
#pragma unroll
        for (int i = 0; i < 2; i++) {
            unsigned dst = as_u32 + (buf * A_WORDS + arow[i] * AS_ST + akg[i]) * 4u;
            size_t off = avalid[i] ? ((size_t)(m0 + arow[i]) * KP + k0 + akg[i]) : 0;
            int sz = avalid[i] ? 16 : 0;
            asm volatile("cp.async.cg.shared.global [%0], [%1], 16, %2;"
                         :: "r"(dst), "l"(AT + off), "r"(sz));
        }
#pragma unroll
        for (int i = 0; i < 2; i++) {
            unsigned dst = bs_u32 + (buf * B_WORDS + brow[i] * BS_ST + bng[i]) * 4u;
            asm volatile("cp.async.cg.shared.global [%0], [%1], 16;"
                         :: "r"(dst), "l"(Wt + (size_t)(k0 + brow[i]) * 128 + bng[i]));
        }
        asm volatile("cp.async.commit_group;");
    };

    float acc[2][8][4];
#pragma unroll
    for (int mt = 0; mt < 2; mt++)
#pragma unroll
        for (int ct = 0; ct < 8; ct++)
#pragma unroll
            for (int j = 0; j < 4; j++) acc[mt][ct][j] = 0.f;

    int KT = KP >> 4;
    stage(0, 0);
    for (int kt = 0; kt < KT; kt++) {
        int buf = kt & 1;
        asm volatile("cp.async.wait_group 0;");
        __syncthreads();   // collective: all threads done reading buf^1 (iter kt-1)
        if (kt + 1 < KT) stage(kt + 1, buf ^ 1);
        const unsigned* Ab = As + buf * A_WORDS;
        const unsigned* Bb = Bs + buf * B_WORDS;
#pragma unroll
        for (int ks = 0; ks < 16; ks += 8) {
            unsigned af[2][4];
#pragma unroll
            for (int mt = 0; mt < 2; mt++) {
                int mb = wr * 32 + mt * 16;
                af[mt][0] = Ab[(mb + gq) * AS_ST + ks + tq];
                af[mt][1] = Ab[(mb + gq + 8) * AS_ST + ks + tq];
                af[mt][2] = Ab[(mb + gq) * AS_ST + ks + tq + 4];
                af[mt][3] = Ab[(mb + gq + 8) * AS_ST + ks + tq + 4];
            }
#pragma unroll
            for (int ct = 0; ct < 8; ct++) {
                int nb = wc * 64 + ct * 8;
                unsigned b0 = Bb[(ks + tq) * BS_ST + nb + gq];
                unsigned b1 = Bb[(ks + tq + 4) * BS_ST + nb + gq];
                mma_tf32(acc[0][ct], af[0], b0, b1);
                mma_tf32(acc[1][ct], af[1], b0, b1);
            }
        }
    }

    if (yb == 0) {
        unsigned* ylh = reinterpret_cast<unsigned*>(g_ylh);
#pragma unroll
        for (int mt = 0; mt < 2; mt++) {
            int r0 = m0 + wr * 32 + mt * 16 + gq;
#pragma unroll
            for (int ct = 0; ct < 8; ct++) {
                int n = wc * 64 + ct * 8 + tq * 2;
                if (r0 < M) {
                    __nv_bfloat162 h = __floats2bfloat162_rn(acc[mt][ct][0], acc[mt][ct][1]);
                    ylh[r0 * 64 + (n >> 1)] = *reinterpret_cast<unsigned*>(&h);
                }
                if (r0 + 8 < M) {
                    __nv_bfloat162 h = __floats2bfloat162_rn(acc[mt][ct][2], acc[mt][ct][3]);
                    ylh[(r0 + 8) * 64 + (n >> 1)] = *reinterpret_cast<unsigned*>(&h);
                }
            }
        }
    } else {
        int osel = (yb == 1) ? osel1 : osel2;
        float* C = reinterpret_cast<float*>(buf_ptr(osel));
#pragma unroll
        for (int mt = 0; mt < 2; mt++) {
            int r0 = m0 + wr * 32 + mt * 16 + gq;
#pragma unroll
            for (int ct = 0; ct < 8; ct++) {
                int n = wc * 64 + ct * 8 + tq * 2;
                float b0v = 0.f, b1v = 0.f;
                if (bp != nullptr) { b0v = bp[n]; b1v = bp[n + 1]; }
                if (r0 < M) {
                    float2 o = make_float2(acc[mt][ct][0] + b0v, acc[mt][ct][1] + b1v);
                    *(float2*)&C[(size_t)r0 * 128 + n] = o;
                }
                if (r0 + 8 < M) {
                    float2 o = make_float2(acc[mt][ct][2] + b0v, acc[mt][ct][3] + b1v);
                    *(float2*)&C[(size_t)(r0 + 8) * 128 + n] = o;
                }
            }
        }
    }
}

// ---------------- aggregation (bf16 gather) + BN + ReLU + residual ----------------
// layer 0: residual from g_res (fp32), result stored ONLY as tf32 (g_h1t4)
// layer 1: residual from g_h1t4 (tf32 bits = valid fp32), result -> y2 only (fused out)
__global__ __launch_bounds__(256) void k_agg(
    int n0, int n1,
    int res_sel,               // BUF_RES or RES_H1T
    int write_t,               // 1: write tf32 h1 table
    const float* __restrict__ bn_g, const float* __restrict__ bn_b,
    const float* __restrict__ bn_m, const float* __restrict__ bn_v,
    int do_out,
    const float* __restrict__ Wl2, const float* __restrict__ Wr2,
    const float* __restrict__ bl2)
{
    const uint2*  __restrict__ ylh = g_ylh;
    const float4* __restrict__ yr  = g_yr;
    const int* __restrict__ col    = g_col;

    int w = n0 + ((blockIdx.x * blockDim.x + threadIdx.x) >> 5);
    int lane = threadIdx.x & 31;
    if (w >= n1) return;
    int s0 = g_rowptr[w], s1 = g_rowptr[w + 1];

    float ax = 0.f, ay = 0.f, az = 0.f, aw = 0.f;
    int e = s0;
    for (; e + 7 < s1; e += 8) {
        uint2 p[8];
#pragma unroll
        for (int u = 0; u < 8; u++) {
            int s = clamp_node(col[e + u]);
            p[u] = ylh[s * 32 + lane];
        }
#pragma unroll
        for (int u = 0; u < 8; u++) {
            float2 f0 = __bfloat1622float2(*reinterpret_cast<__nv_bfloat162*>(&p[u].x));
            float2 f1 = __bfloat1622float2(*reinterpret_cast<__nv_bfloat162*>(&p[u].y));
            ax += f0.x; ay += f0.y; az += f1.x; aw += f1.y;
        }
    }
    for (; e < s1; e++) {
        int s = clamp_node(col[e]);
        uint2 p = ylh[s * 32 + lane];
        float2 f0 = __bfloat1622float2(*reinterpret_cast<__nv_bfloat162*>(&p.x));
        float2 f1 = __bfloat1622float2(*reinterpret_cast<__nv_bfloat162*>(&p.y));
        ax += f0.x; ay += f0.y; az += f1.x; aw += f1.y;
    }

    int deg = s1 - s0;
    float inv = 1.f / (float)(deg > 1 ? deg : 1);
    float4 r = yr[w * 32 + lane];
    int f = lane * 4;
    float gx = bn_g[f], gy = bn_g[f + 1], gz = bn_g[f + 2], gw = bn_g[f + 3];
    float bx = bn_b[f], by = bn_b[f + 1], bz = bn_b[f + 2], bw = bn_b[f + 3];
    float mx = bn_m[f], my = bn_m[f + 1], mz = bn_m[f + 2], mw = bn_m[f + 3];
    float qx = bn_v[f], qy = bn_v[f + 1], qz = bn_v[f + 2], qw = bn_v[f + 3];

    float4 rr;
    if (res_sel == RES_H1T) {
        uint4 t = g_h1t4[w * 32 + lane];
        rr = make_float4(__uint_as_float(t.x), __uint_as_float(t.y),
                         __uint_as_float(t.z), __uint_as_float(t.w));
    } else {
        rr = g_res[w * 32 + lane];
    }

    float sx = gx * rsqrtf(qx + BN_EPS);
    float sy = gy * rsqrtf(qy + BN_EPS);
    float sz = gz * rsqrtf(qz + BN_EPS);
    float sw = gw * rsqrtf(qw + BN_EPS);

    float vx = (ax * inv + r.x - mx) * sx + bx;
    float vy = (ay * inv + r.y - my) * sy + by;
    float vz = (az * inv + r.z - mz) * sz + bz;
    float vw = (aw * inv + r.w - mw) * sw + bw;
    vx = fmaxf(vx, 0.f) + rr.x;
    vy = fmaxf(vy, 0.f) + rr.y;
    vz = fmaxf(vz, 0.f) + rr.z;
    vw = fmaxf(vw, 0.f) + rr.w;

    if (write_t) {
        uint4 t;
        t.x = f2tf32(vx); t.y = f2tf32(vy); t.z = f2tf32(vz); t.w = f2tf32(vw);
        g_h1t4[w * 32 + lane] = t;
    }

    if (do_out) {
        float a0 = Wl2[f], a1 = Wl2[f + 1], a2 = Wl2[f + 2], a3 = Wl2[f + 3];
        float b0 = Wl2[128 + f], b1 = Wl2[128 + f + 1], b2 = Wl2[128 + f + 2], b3 = Wl2[128 + f + 3];
        float c0 = Wr2[f], c1 = Wr2[f + 1], c2 = Wr2[f + 2], c3 = Wr2[f + 3];
        float e0 = Wr2[128 + f], e1 = Wr2[128 + f + 1], e2 = Wr2[128 + f + 2], e3 = Wr2[128 + f + 3];
        float d0 = vx * a0 + vy * a1 + vz * a2 + vw * a3;
        float d1 = vx * b0 + vy * b1 + vz * b2 + vw * b3;
        float d2 = vx * c0 + vy * c1 + vz * c2 + vw * c3;
        float d3 = vx * e0 + vy * e1 + vz * e2 + vw * e3;
#pragma unroll
        for (int off = 16; off; off >>= 1) {
            d0 += __shfl_xor_sync(0xffffffffu, d0, off);
            d1 += __shfl_xor_sync(0xffffffffu, d1, off);
            d2 += __shfl_xor_sync(0xffffffffu, d2, off);
            d3 += __shfl_xor_sync(0xffffffffu, d3, off);
        }
        if (lane == 0) {
            g_y2[w] = make_float4(d0, d1, d2 + bl2[0], d3 + bl2[1]);
        }
    }
}

// ---------------- final: aggregate 2-wide logits + root term ----------------
__global__ void k_final(float* __restrict__ out)
{
    int i = blockIdx.x * blockDim.x + threadIdx.x;
    if (i >= NN) return;
    int s0 = g_rowptr[i], s1 = g_rowptr[i + 1];
    float a0 = 0.f, a1 = 0.f;
    int e = s0;
    for (; e + 3 < s1; e += 4) {
        float4 v0 = g_y2[clamp_node(g_col[e])];
        float4 v1 = g_y2[clamp_node(g_col[e + 1])];
        float4 v2 = g_y2[clamp_node(g_col[e + 2])];
        float4 v3 = g_y2[clamp_node(g_col[e + 3])];
        a0 += v0.x + v1.x + v2.x + v3.x;
        a1 += v0.y + v1.y + v2.y + v3.y;
    }
    for (; e < s1; e++) {
        float4 v = g_y2[clamp_node(g_col[e])];
        a0 += v.x;
        a1 += v.y;
    }
    int deg = s1 - s0;
    float inv = 1.f / (float)(deg > 1 ? deg : 1);
    float4 self = g_y2[i];
    out[2 * i + 0] = a0 * inv + self.z;
    out[2 * i + 1] = a1 * inv + self.w;
}

// ---------------- launch ----------------
extern "C" void kernel_launch(void* const* d_in, const int* in_sizes, int n_in,
                              void* d_out, int out_size)
{
    const float* x     = (const float*)d_in[0];
    const void*  ei    = (const void*)d_in[1];
    const float* Wl0   = (const float*)d_in[2];
    const float* bl0   = (const float*)d_in[3];
    const float* Wr0   = (const float*)d_in[4];
    const float* Wl1   = (const float*)d_in[5];
    const float* bl1   = (const float*)d_in[6];
    const float* Wr1   = (const float*)d_in[7];
    const float* Wl2   = (const float*)d_in[8];
    const float* bl2   = (const float*)d_in[9];
    const float* Wr2   = (const float*)d_in[10];
    const float* Wres0 = (const float*)d_in[11];
    const float* bn0_g = (const float*)d_in[12];
    const float* bn0_b = (const float*)d_in[13];
    const float* bn0_m = (const float*)d_in[14];
    const float* bn0_v = (const float*)d_in[15];
    const float* bn1_g = (const float*)d_in[16];
    const float* bn1_b = (const float*)d_in[17];
    const float* bn1_m = (const float*)d_in[18];
    const float* bn1_v = (const float*)d_in[19];

    const int off0l = 0;
    const int off0r = W0SZ;
    const int off0s = 2 * W0SZ;
    const int off1l = 3 * W0SZ;
    const int off1r = 3 * W0SZ + W1SZ;

    cudaStream_t s2;
    cudaStreamCreateWithFlags(&s2, cudaStreamNonBlocking);
    cudaEvent_t evFork, evDense, evCSR, evHalf1;
    cudaEventCreateWithFlags(&evFork,  cudaEventDisableTiming);
    cudaEventCreateWithFlags(&evDense, cudaEventDisableTiming);
    cudaEventCreateWithFlags(&evCSR,   cudaEventDisableTiming);
    cudaEventCreateWithFlags(&evHalf1, cudaEventDisableTiming);

    // fork
    cudaEventRecord(evFork, 0);
    cudaStreamWaitEvent(s2, evFork, 0);

    int gx_all = (NN + 127) / 128;
    int ptotal = XT_TOTAL + WT_TOTAL;

    // enqueue order keeps gemm0 as host-launch #4 (ncu window)
    e_cvt_hist<<<(NE + 255) / 256, 256>>>(ei);                                        // #1 s0
    k_scan1<<<SCAN_NB, 256>>>();                                                      // #2 s0
    k_prep<<<(ptotal + 255) / 256, 256, 0, s2>>>(x, Wl0, Wr0, Wres0, Wl1, Wr1);       // #3 s2
    k_gemm_tc<<<dim3(gx_all, 3), 256, 0, s2>>>(0, 0, off0l, off0r, off0s,
                                               BUF_YR, BUF_RES, bl0, NN);             // #4 s2
    cudaEventRecord(evDense, s2);
    k_scan23<<<SCAN_NB, 256>>>();                                                     // #5 s0
    k_scatter<<<(NE + 255) / 256, 256>>>();                                           // #6 s0
    cudaEventRecord(evCSR, 0);

    // cross joins
    cudaStreamWaitEvent(0, evDense, 0);
    cudaStreamWaitEvent(s2, evCSR, 0);

    // ---- pipelined layer-0 agg + layer-1 GEMM, split by node halves ----
    int blk_h0 = (H0 * 32 + 255) / 256;
    int blk_h1 = ((NN - H0) * 32 + 255) / 256;
    int gx_h0 = H0 / 128;
    int gx_h1 = (NN - H0 + 127) / 128;

    k_agg<<<blk_h0, 256>>>(0, H0, BUF_RES, 1, bn0_g, bn0_b, bn0_m, bn0_v,
                           0, nullptr, nullptr, nullptr);
    k_gemm_tc<<<dim3(gx_h0, 2), 256>>>(1, 0, off1l, off1r, off1r,
                                       BUF_YR, BUF_YR, bl1, NN);
    k_agg<<<blk_h1, 256, 0, s2>>>(H0, NN, BUF_RES, 1, bn0_g, bn0_b, bn0_m, bn0_v,
                                  0, nullptr, nullptr, nullptr);
    k_gemm_tc<<<dim3(gx_h1, 2), 256, 0, s2>>>(1, H0, off1l, off1r, off1r,
                                              BUF_YR, BUF_YR, bl1, NN);
    cudaEventRecord(evHalf1, s2);
    cudaStreamWaitEvent(0, evHalf1, 0);

    // ---- layer-1 aggregate + fused output layer (y2 only), then final ----
    int blk_all = (NN * 32 + 255) / 256;
    k_agg<<<blk_all, 256>>>(0, NN, RES_H1T, 0, bn1_g, bn1_b, bn1_m, bn1_v,
                            1, Wl2, Wr2, bl2);
    k_final<<<(NN + 255) / 256, 256>>>((float*)d_out);
}